// round 14
// baseline (speedup 1.0000x reference)
#include <cuda_runtime.h>
#include <cstdint>
#include <math.h>
#include <mma.h>

using namespace nvcuda;

// Problem constants
static constexpr int NN  = 50000;    // nodes
static constexpr int EE  = 800000;   // edges
static constexpr int DD  = 128;      // feature dim (= H*C)
static constexpr int HH  = 8;        // heads
static constexpr int HIDN = 512;     // FFN hidden
static constexpr int EDD = 32;       // edge attr dim

// ---------------- device scratch (static, no allocations) ----------------
__device__ float g_act[(size_t)NN * HIDN];
__device__ float g_u[(size_t)NN * DD];
__device__ float g_v[(size_t)NN * DD];
__device__ float g_xl[(size_t)NN * DD];
__device__ float g_xr[(size_t)NN * DD];
__device__ float g_logits[(size_t)EE * HH];   // CSR-ordered: [pos][h]
__device__ int   g_src[EE];
__device__ int   g_dst[EE];
__device__ int   g_pos[EE];                   // edge -> csr slot
__device__ int   g_src_csr[EE];               // csr slot -> src node
__device__ int   g_deg[NN];
__device__ int   g_rowstart[NN + 1];
__device__ int   g_cursor[NN];
__device__ int   g_eids[EE];                  // csr slot -> edge id
__device__ int   g_is64;
__device__ int   g_bsum[256];
__device__ int   g_boff[260];

// ---------------- cp.async helpers ----------------
__device__ __forceinline__ void cp16(void* dst, const void* src) {
    unsigned int d = (unsigned int)__cvta_generic_to_shared(dst);
    asm volatile("cp.async.cg.shared.global [%0], [%1], 16;" :: "r"(d), "l"(src));
}
__device__ __forceinline__ void cp_commit() {
    asm volatile("cp.async.commit_group;" ::: "memory");
}
__device__ __forceinline__ void cp_wait1() {
    asm volatile("cp.async.wait_group 1;" ::: "memory");
}

// ---------------- index dtype detection + CSR build ----------------
__global__ void k_detect(const void* ei) {
    const long long* p = (const long long*)ei;
    int ok = 1;
    for (int i = 0; i < 64; i++) {
        long long v = p[i];
        if (v < 0 || v >= (long long)NN) { ok = 0; break; }
    }
    g_is64 = ok;
}

__global__ void k_zero_deg() {
    int i = blockIdx.x * 256 + threadIdx.x;
    if (i < NN) g_deg[i] = 0;
}

__global__ void k_convert(const void* ei) {
    int e = blockIdx.x * 256 + threadIdx.x;
    if (e >= EE) return;
    int s, d;
    if (g_is64) {
        const long long* p = (const long long*)ei;
        s = (int)p[e]; d = (int)p[EE + e];
    } else {
        const int* p = (const int*)ei;
        s = p[e]; d = p[EE + e];
    }
    g_src[e] = s;
    g_dst[e] = d;
    atomicAdd(&g_deg[d], 1);
}

__global__ void k_scan1() {
    __shared__ int wsum[8];
    int b = blockIdx.x, t = threadIdx.x;
    int i = b * 256 + t;
    int v = (i < NN) ? g_deg[i] : 0;
    int x = v;
#pragma unroll
    for (int off = 1; off < 32; off <<= 1) {
        int y = __shfl_up_sync(0xffffffffu, x, off);
        if ((t & 31) >= off) x += y;
    }
    if ((t & 31) == 31) wsum[t >> 5] = x;
    __syncthreads();
    if (t < 8) {
        int s = wsum[t];
#pragma unroll
        for (int off = 1; off < 8; off <<= 1) {
            int y = __shfl_up_sync(0xffu, s, off);
            if (t >= off) s += y;
        }
        wsum[t] = s;
    }
    __syncthreads();
    int woff = (t >= 32) ? wsum[(t >> 5) - 1] : 0;
    int incl = x + woff;
    if (i < NN) g_rowstart[i] = incl - v;
    if (t == 255) g_bsum[b] = incl;
}

__global__ void k_scan2(int nblk) {
    __shared__ int wsum[8];
    int t = threadIdx.x;
    int v = (t < nblk) ? g_bsum[t] : 0;
    int x = v;
#pragma unroll
    for (int off = 1; off < 32; off <<= 1) {
        int y = __shfl_up_sync(0xffffffffu, x, off);
        if ((t & 31) >= off) x += y;
    }
    if ((t & 31) == 31) wsum[t >> 5] = x;
    __syncthreads();
    if (t < 8) {
        int s = wsum[t];
#pragma unroll
        for (int off = 1; off < 8; off <<= 1) {
            int y = __shfl_up_sync(0xffu, s, off);
            if (t >= off) s += y;
        }
        wsum[t] = s;
    }
    __syncthreads();
    int woff = (t >= 32) ? wsum[(t >> 5) - 1] : 0;
    int incl = x + woff;
    g_boff[t] = incl - v;
    if (t == 255) g_boff[256] = incl;
}

__global__ void k_scan3() {
    int b = blockIdx.x, t = threadIdx.x;
    int i = b * 256 + t;
    if (i < NN) {
        int r = g_rowstart[i] + g_boff[b];
        g_rowstart[i] = r;
        g_cursor[i] = r;
    }
    if (b == 0 && t == 0) g_rowstart[NN] = g_boff[256];
}

__global__ void k_scatter() {
    int e = blockIdx.x * 256 + threadIdx.x;
    if (e >= EE) return;
    int d = g_dst[e];
    int pos = atomicAdd(&g_cursor[d], 1);
    g_eids[pos] = e;
    g_pos[e] = pos;
    g_src_csr[pos] = g_src[e];
}

// ---------------- TF32 GEMM (dual mode + optional relu), cp.async double-buffered ----------------
// block tile 128x128, K-step 32, 4 warps (2x2), warp tile 64x64
static constexpr int LDA = 36;
static constexpr int LDB = 132;
static constexpr int LDS = 132;
static constexpr int GEMM_SMEM = (2 * 128 * LDA + 2 * 32 * LDB) * 4;  // 70656 B

template <bool RELU>
__global__ void __launch_bounds__(128, 2)
k_gemm_tf32(const float* __restrict__ A, const float* B,
            const float* bias, float* Cout,
            int M, int Nc, int K,
            const float* B2, const float* bias2, float* Cout2)
{
    extern __shared__ float sm[];
    float* As = sm;
    float* Bs = sm + 2 * 128 * LDA;

    int tid = threadIdx.x;
    int wid = tid >> 5;
    int row0 = blockIdx.y * 128;
    int col0;
    if (B2) {
        col0 = 0;
        if (blockIdx.x) { B = B2; bias = bias2; Cout = Cout2; }
    } else {
        col0 = blockIdx.x * 128;
    }
    int warp_m = wid >> 1;
    int warp_n = wid & 1;

    wmma::fragment<wmma::accumulator, 16, 16, 8, float> acc[4][4];
#pragma unroll
    for (int i = 0; i < 4; i++)
#pragma unroll
        for (int j = 0; j < 4; j++) wmma::fill_fragment(acc[i][j], 0.f);

    const int NKt = K >> 5;

    auto load_tile = [&](int kt, int buf) {
        float* Ad = As + buf * 128 * LDA;
        float* Bd = Bs + buf * 32 * LDB;
#pragma unroll
        for (int j = 0; j < 8; j++) {
            int idx = tid + j * 128;
            int r = idx >> 3;
            int c4 = (idx & 7) << 2;
            int rr = row0 + r;
            rr = (rr < M) ? rr : 0;
            cp16(Ad + r * LDA + c4, A + (size_t)rr * K + (kt << 5) + c4);
        }
#pragma unroll
        for (int j = 0; j < 8; j++) {
            int idx = tid + j * 128;
            int r = idx >> 5;
            int c4 = (idx & 31) << 2;
            cp16(Bd + r * LDB + c4, B + (size_t)((kt << 5) + r) * Nc + col0 + c4);
        }
    };

    load_tile(0, 0);
    cp_commit();

    for (int kt = 0; kt < NKt; kt++) {
        int buf = kt & 1;
        if (kt + 1 < NKt) load_tile(kt + 1, buf ^ 1);
        cp_commit();
        cp_wait1();
        __syncthreads();

        float* Ab = As + buf * 128 * LDA;
        float* Bb = Bs + buf * 32 * LDB;
#pragma unroll
        for (int kk = 0; kk < 4; kk++) {
            wmma::fragment<wmma::matrix_a, 16, 16, 8, wmma::precision::tf32, wmma::row_major> af[4];
            wmma::fragment<wmma::matrix_b, 16, 16, 8, wmma::precision::tf32, wmma::row_major> bf[4];
#pragma unroll
            for (int i = 0; i < 4; i++) {
                wmma::load_matrix_sync(af[i], Ab + (warp_m * 64 + i * 16) * LDA + kk * 8, LDA);
#pragma unroll
                for (int t = 0; t < af[i].num_elements; t++)
                    af[i].x[t] = wmma::__float_to_tf32(af[i].x[t]);
            }
#pragma unroll
            for (int j = 0; j < 4; j++) {
                wmma::load_matrix_sync(bf[j], Bb + (kk * 8) * LDB + warp_n * 64 + j * 16, LDB);
#pragma unroll
                for (int t = 0; t < bf[j].num_elements; t++)
                    bf[j].x[t] = wmma::__float_to_tf32(bf[j].x[t]);
            }
#pragma unroll
            for (int i = 0; i < 4; i++)
#pragma unroll
                for (int j = 0; j < 4; j++)
                    wmma::mma_sync(acc[i][j], af[i], bf[j], acc[i][j]);
        }
        __syncthreads();
    }

    float* St = As;
#pragma unroll
    for (int ph = 0; ph < 2; ph++) {
        if (warp_m == ph) {
#pragma unroll
            for (int i = 0; i < 4; i++)
#pragma unroll
                for (int j = 0; j < 4; j++)
                    wmma::store_matrix_sync(St + (i * 16) * LDS + warp_n * 64 + j * 16,
                                            acc[i][j], LDS, wmma::mem_row_major);
        }
        __syncthreads();
#pragma unroll
        for (int j = 0; j < 16; j++) {
            int idx = tid + j * 128;
            int lr = idx >> 5;
            int cc = (idx & 31) << 2;
            int g = row0 + ph * 64 + lr;
            if (g < M) {
                float4 o = *(float4*)(St + lr * LDS + cc);
                int c = col0 + cc;
                o.x += bias[c + 0]; o.y += bias[c + 1];
                o.z += bias[c + 2]; o.w += bias[c + 3];
                if (RELU) {
                    o.x = fmaxf(o.x, 0.f); o.y = fmaxf(o.y, 0.f);
                    o.z = fmaxf(o.z, 0.f); o.w = fmaxf(o.w, 0.f);
                }
                *(float4*)(Cout + (size_t)g * Nc + c) = o;
            }
        }
        __syncthreads();
    }
}

// ---------------- v = LayerNorm(h + u) ----------------
__global__ void k_ln_v(const float* __restrict__ h,
                       const float* __restrict__ g, const float* __restrict__ b)
{
    int row = blockIdx.x * 8 + (threadIdx.x >> 5);
    if (row >= NN) return;
    int lane = threadIdx.x & 31;
    const float4* hp = (const float4*)(h + (size_t)row * DD);
    const float4* up = (const float4*)(g_u + (size_t)row * DD);
    float4 hv = hp[lane], uv = up[lane];
    float x0 = hv.x + uv.x, x1 = hv.y + uv.y, x2 = hv.z + uv.z, x3 = hv.w + uv.w;
    float s  = x0 + x1 + x2 + x3;
    float s2 = x0 * x0 + x1 * x1 + x2 * x2 + x3 * x3;
#pragma unroll
    for (int off = 16; off >= 1; off >>= 1) {
        s  += __shfl_xor_sync(0xffffffffu, s,  off);
        s2 += __shfl_xor_sync(0xffffffffu, s2, off);
    }
    float mu  = s * (1.f / 128.f);
    float var = s2 * (1.f / 128.f) - mu * mu;
    float r   = rsqrtf(var + 1e-5f);
    float4 gv = ((const float4*)g)[lane];
    float4 bv = ((const float4*)b)[lane];
    float4 o;
    o.x = (x0 - mu) * r * gv.x + bv.x;
    o.y = (x1 - mu) * r * gv.y + bv.y;
    o.z = (x2 - mu) * r * gv.z + bv.z;
    o.w = (x3 - mu) * r * gv.w + bv.w;
    ((float4*)(g_v + (size_t)row * DD))[lane] = o;
}

// ---------------- edge logits: wmma xe (128 edges/block) + warp-per-edge float4 finish ----------------
static constexpr int EPB = 128;
static constexpr int LDEA = 36;
static constexpr int LDWE = 132;
static constexpr int LDXE = 132;
static constexpr int EDGE_SMEM = (EPB * LDEA + EDD * LDWE + EPB * LDXE + 128) * 4; // 103424 B

__global__ void __launch_bounds__(256)
k_edge_logits(const float* __restrict__ edge_attr,
              const float* __restrict__ We, const float* __restrict__ att)
{
    extern __shared__ float sm[];
    float* ea_sh  = sm;
    float* We_sh  = ea_sh + EPB * LDEA;
    float* xe_sh  = We_sh + EDD * LDWE;
    float* att_sh = xe_sh + EPB * LDXE;

    int tid = threadIdx.x;
    int e0 = blockIdx.x * EPB;

    // edge_attr tile: 128 edges x 32 attrs = 1024 f4 (4/thread)
#pragma unroll
    for (int j = 0; j < 4; j++) {
        int idx = tid + j * 256;
        int r = idx >> 3;
        int cc = (idx & 7) << 2;
        float4 v = *(const float4*)(edge_attr + (size_t)(e0 + r) * EDD + cc);
        *(float4*)(ea_sh + r * LDEA + cc) = v;
    }
    // We: 32x128 = 1024 f4 (4/thread)
#pragma unroll
    for (int j = 0; j < 4; j++) {
        int idx = tid + j * 256;
        int r = idx >> 5;
        int cc = (idx & 31) << 2;
        float4 v = *(const float4*)(We + (size_t)r * 128 + cc);
        *(float4*)(We_sh + r * LDWE + cc) = v;
    }
    if (tid < 128) att_sh[tid] = att[tid];
    __syncthreads();

    // xe = ea @ We : m=128, n=128, k=32 (8 warps 4x2, warp tile 32x64)
    {
        int wid = tid >> 5;
        int warp_m = wid >> 1;   // 0..3
        int warp_n = wid & 1;    // 0..1
        wmma::fragment<wmma::accumulator, 16, 16, 8, float> acc[2][4];
#pragma unroll
        for (int i = 0; i < 2; i++)
#pragma unroll
            for (int j = 0; j < 4; j++) wmma::fill_fragment(acc[i][j], 0.f);
#pragma unroll
        for (int kk = 0; kk < 4; kk++) {
            wmma::fragment<wmma::matrix_a, 16, 16, 8, wmma::precision::tf32, wmma::row_major> af[2];
            wmma::fragment<wmma::matrix_b, 16, 16, 8, wmma::precision::tf32, wmma::row_major> bf[4];
#pragma unroll
            for (int i = 0; i < 2; i++) {
                wmma::load_matrix_sync(af[i], ea_sh + (warp_m * 32 + i * 16) * LDEA + kk * 8, LDEA);
#pragma unroll
                for (int t = 0; t < af[i].num_elements; t++)
                    af[i].x[t] = wmma::__float_to_tf32(af[i].x[t]);
            }
#pragma unroll
            for (int j = 0; j < 4; j++) {
                wmma::load_matrix_sync(bf[j], We_sh + (kk * 8) * LDWE + warp_n * 64 + j * 16, LDWE);
#pragma unroll
                for (int t = 0; t < bf[j].num_elements; t++)
                    bf[j].x[t] = wmma::__float_to_tf32(bf[j].x[t]);
            }
#pragma unroll
            for (int i = 0; i < 2; i++)
#pragma unroll
                for (int j = 0; j < 4; j++)
                    wmma::mma_sync(acc[i][j], af[i], bf[j], acc[i][j]);
        }
#pragma unroll
        for (int i = 0; i < 2; i++)
#pragma unroll
            for (int j = 0; j < 4; j++)
                wmma::store_matrix_sync(xe_sh + (warp_m * 32 + i * 16) * LDXE + warp_n * 64 + j * 16,
                                        acc[i][j], LDXE, wmma::mem_row_major);
    }
    __syncthreads();

    // finish: warp-per-edge, float4 per lane
    {
        int wid  = tid >> 5;
        int lane = tid & 31;
        int c4 = lane << 2;
        float4 attv = *(float4*)(att_sh + c4);

#pragma unroll
        for (int it = 0; it < EPB / 8; it++) {
            int le = it * 8 + wid;
            int e  = e0 + le;
            int s  = g_src[e];
            int d  = g_dst[e];
            float4 xe4 = *(float4*)(xe_sh + le * LDXE + c4);
            float4 xl4 = *(const float4*)(g_xl + (size_t)s * DD + c4);
            float4 xr4 = *(const float4*)(g_xr + (size_t)d * DD + c4);
            float x0 = xe4.x + xl4.x + xr4.x;
            float x1 = xe4.y + xl4.y + xr4.y;
            float x2 = xe4.z + xl4.z + xr4.z;
            float x3 = xe4.w + xl4.w + xr4.w;
            x0 = (x0 > 0.f) ? x0 : 0.2f * x0;
            x1 = (x1 > 0.f) ? x1 : 0.2f * x1;
            x2 = (x2 > 0.f) ? x2 : 0.2f * x2;
            x3 = (x3 > 0.f) ? x3 : 0.2f * x3;
            float p = x0 * attv.x + x1 * attv.y + x2 * attv.z + x3 * attv.w;
            p += __shfl_down_sync(0xffffffffu, p, 2);
            p += __shfl_down_sync(0xffffffffu, p, 1);
            if ((lane & 3) == 0) {
                int pos = g_pos[e];
                g_logits[(size_t)pos * HH + (lane >> 2)] = p;
            }
        }
    }
}

// ---------------- per-node softmax + aggregation + LN (shuffle reductions, __expf) ----------------
__global__ void __launch_bounds__(128)
k_node(const float* __restrict__ bias_out,
       const float* __restrict__ ln_g, const float* __restrict__ ln_b,
       float* __restrict__ out, float* __restrict__ alpha_out)
{
    __shared__ float swarp[32];
    __shared__ float sacc[4 * 128];
    __shared__ float invden[8];

    int n   = blockIdx.x;
    int tid = threadIdx.x;
    int wid  = tid >> 5;
    int lane = tid & 31;
    int start = g_rowstart[n];
    int deg   = g_rowstart[n + 1] - start;

    float s = 0.f;
    size_t base = (size_t)start * HH;
    for (int idx = tid; idx < deg * HH; idx += 128)
        s += __expf(g_logits[base + idx]);
    s += __shfl_xor_sync(0xffffffffu, s, 16);
    s += __shfl_xor_sync(0xffffffffu, s, 8);
    if (lane < 8) swarp[wid * 8 + lane] = s;
    __syncthreads();
    if (tid < 8) {
        float t = swarp[tid] + swarp[8 + tid] + swarp[16 + tid] + swarp[24 + tid];
        invden[tid] = (t > 0.f) ? 1.f / t : 0.f;
    }
    __syncthreads();

    int c4 = lane << 2;
    int hd = lane >> 2;
    float id2 = invden[hd];
    float4 acc4 = make_float4(0.f, 0.f, 0.f, 0.f);
    for (int i = wid; i < deg; i += 4) {
        int p = start + i;
        float a = __expf(g_logits[(size_t)p * HH + hd]) * id2;
        int srcn = g_src_csr[p];
        if ((lane & 3) == 0) alpha_out[(size_t)g_eids[p] * HH + hd] = a;
        float4 x = *(const float4*)(g_xl + (size_t)srcn * DD + c4);
        acc4.x = fmaf(a, x.x, acc4.x);
        acc4.y = fmaf(a, x.y, acc4.y);
        acc4.z = fmaf(a, x.z, acc4.z);
        acc4.w = fmaf(a, x.w, acc4.w);
    }
    *(float4*)(sacc + wid * 128 + c4) = acc4;
    __syncthreads();

    int c = tid;
    float wv = sacc[c] + sacc[128 + c] + sacc[256 + c] + sacc[384 + c]
             + bias_out[c] + g_v[(size_t)n * DD + c];

    float r1 = wv;
#pragma unroll
    for (int off = 16; off >= 1; off >>= 1)
        r1 += __shfl_xor_sync(0xffffffffu, r1, off);
    if (lane == 0) swarp[wid] = r1;
    __syncthreads();
    float mu = (swarp[0] + swarp[1] + swarp[2] + swarp[3]) * (1.f / 128.f);
    float dv = wv - mu;
    float r2 = dv * dv;
#pragma unroll
    for (int off = 16; off >= 1; off >>= 1)
        r2 += __shfl_xor_sync(0xffffffffu, r2, off);
    __syncthreads();
    if (lane == 0) swarp[wid] = r2;
    __syncthreads();
    float var = (swarp[0] + swarp[1] + swarp[2] + swarp[3]) * (1.f / 128.f);
    float r = rsqrtf(var + 1e-5f);
    out[(size_t)n * DD + c] = dv * r * ln_g[c] + ln_b[c];
}

// ---------------- launch ----------------
extern "C" void kernel_launch(void* const* d_in, const int* in_sizes, int n_in,
                              void* d_out, int out_size)
{
    const float* h_ptr     = (const float*)d_in[0];
    const void*  ei        = d_in[1];
    const float* edge_attr = (const float*)d_in[2];
    const float* w1        = (const float*)d_in[3];
    const float* b1        = (const float*)d_in[4];
    const float* w2        = (const float*)d_in[5];
    const float* b2        = (const float*)d_in[6];
    const float* ln_g      = (const float*)d_in[7];
    const float* ln_b      = (const float*)d_in[8];
    const float* Wl        = (const float*)d_in[9];
    const float* bl        = (const float*)d_in[10];
    const float* Wr        = (const float*)d_in[11];
    const float* br        = (const float*)d_in[12];
    const float* We        = (const float*)d_in[13];
    const float* att       = (const float*)d_in[14];
    const float* bias_out  = (const float*)d_in[15];

    float* out = (float*)d_out;
    float* alpha_out = out + ((size_t)out_size - (size_t)EE * HH);

    void *p_act, *p_u, *p_v, *p_xl, *p_xr;
    cudaGetSymbolAddress(&p_act, g_act);
    cudaGetSymbolAddress(&p_u,   g_u);
    cudaGetSymbolAddress(&p_v,   g_v);
    cudaGetSymbolAddress(&p_xl,  g_xl);
    cudaGetSymbolAddress(&p_xr,  g_xr);
    float* act = (float*)p_act;
    float* u   = (float*)p_u;
    float* v   = (float*)p_v;
    float* xl  = (float*)p_xl;
    float* xr  = (float*)p_xr;

    cudaFuncSetAttribute(k_gemm_tf32<true>,  cudaFuncAttributeMaxDynamicSharedMemorySize, GEMM_SMEM);
    cudaFuncSetAttribute(k_gemm_tf32<false>, cudaFuncAttributeMaxDynamicSharedMemorySize, GEMM_SMEM);
    cudaFuncSetAttribute(k_edge_logits,      cudaFuncAttributeMaxDynamicSharedMemorySize, EDGE_SMEM);

    int nblk = (NN + 255) / 256;  // 196

    k_zero_deg<<<nblk, 256>>>();
    k_detect<<<1, 1>>>(ei);
    k_convert<<<(EE + 255) / 256, 256>>>(ei);

    // profiled slot #4 -> FFN1
    dim3 g1(HIDN / 128, (NN + 127) / 128);
    k_gemm_tf32<true><<<g1, 128, GEMM_SMEM>>>(h_ptr, w1, b1, act, NN, HIDN, DD,
                                              nullptr, nullptr, nullptr);

    k_scan1<<<nblk, 256>>>();
    k_scan2<<<1, 256>>>(nblk);
    k_scan3<<<nblk, 256>>>();
    k_scatter<<<(EE + 255) / 256, 256>>>();

    // FFN2 (plain GEMM) + separate LN (R10 config — fusions regressed)
    dim3 g2(DD / 128, (NN + 127) / 128);
    k_gemm_tf32<false><<<g2, 128, GEMM_SMEM>>>(act, w2, b2, u, NN, DD, HIDN,
                                               nullptr, nullptr, nullptr);
    k_ln_v<<<(NN + 7) / 8, 256>>>(h_ptr, ln_g, ln_b);

    // fused Wl/Wr projection
    dim3 gd(2, (NN + 127) / 128);
    k_gemm_tf32<false><<<gd, 128, GEMM_SMEM>>>(v, Wl, bl, xl, NN, DD, DD, Wr, br, xr);

    k_edge_logits<<<EE / EPB, 256, EDGE_SMEM>>>(edge_attr, We, att);

    k_node<<<NN, 128>>>(bias_out, ln_g, ln_b, out, alpha_out);
}

// round 15
// speedup vs baseline: 1.4001x; 1.4001x over previous
#include <cuda_runtime.h>
#include <cstdint>
#include <math.h>
#include <mma.h>

using namespace nvcuda;

// Problem constants
static constexpr int NN  = 50000;    // nodes
static constexpr int EE  = 800000;   // edges
static constexpr int DD  = 128;      // feature dim (= H*C)
static constexpr int HH  = 8;        // heads
static constexpr int HIDN = 512;     // FFN hidden
static constexpr int EDD = 32;       // edge attr dim

// ---------------- device scratch (static, no allocations) ----------------
__device__ float g_act[(size_t)NN * HIDN];
__device__ float g_u[(size_t)NN * DD];
__device__ float g_v[(size_t)NN * DD];
__device__ float g_xl[(size_t)NN * DD];
__device__ float g_xr[(size_t)NN * DD];
__device__ float g_logits[(size_t)EE * HH];   // CSR-ordered: [pos][h]
__device__ int   g_src[EE];
__device__ int   g_dst[EE];
__device__ int   g_pos[EE];                   // edge -> csr slot
__device__ int   g_src_csr[EE];               // csr slot -> src node
__device__ int   g_deg[NN];
__device__ int   g_rowstart[NN + 1];
__device__ int   g_cursor[NN];
__device__ int   g_eids[EE];                  // csr slot -> edge id
__device__ int   g_is64;
__device__ int   g_bsum[256];
__device__ int   g_boff[260];

// ---------------- cp.async helpers ----------------
__device__ __forceinline__ void cp16(void* dst, const void* src) {
    unsigned int d = (unsigned int)__cvta_generic_to_shared(dst);
    asm volatile("cp.async.cg.shared.global [%0], [%1], 16;" :: "r"(d), "l"(src));
}
__device__ __forceinline__ void cp_commit() {
    asm volatile("cp.async.commit_group;" ::: "memory");
}
__device__ __forceinline__ void cp_wait1() {
    asm volatile("cp.async.wait_group 1;" ::: "memory");
}

// ---------------- index dtype detection + CSR build ----------------
__global__ void k_detect(const void* ei) {
    const long long* p = (const long long*)ei;
    int ok = 1;
    for (int i = 0; i < 64; i++) {
        long long v = p[i];
        if (v < 0 || v >= (long long)NN) { ok = 0; break; }
    }
    g_is64 = ok;
}

__global__ void k_zero_deg() {
    int i = blockIdx.x * 256 + threadIdx.x;
    if (i < NN) g_deg[i] = 0;
}

__global__ void k_convert(const void* ei) {
    int e = blockIdx.x * 256 + threadIdx.x;
    if (e >= EE) return;
    int s, d;
    if (g_is64) {
        const long long* p = (const long long*)ei;
        s = (int)p[e]; d = (int)p[EE + e];
    } else {
        const int* p = (const int*)ei;
        s = p[e]; d = p[EE + e];
    }
    g_src[e] = s;
    g_dst[e] = d;
    atomicAdd(&g_deg[d], 1);
}

__global__ void k_scan1() {
    __shared__ int wsum[8];
    int b = blockIdx.x, t = threadIdx.x;
    int i = b * 256 + t;
    int v = (i < NN) ? g_deg[i] : 0;
    int x = v;
#pragma unroll
    for (int off = 1; off < 32; off <<= 1) {
        int y = __shfl_up_sync(0xffffffffu, x, off);
        if ((t & 31) >= off) x += y;
    }
    if ((t & 31) == 31) wsum[t >> 5] = x;
    __syncthreads();
    if (t < 8) {
        int s = wsum[t];
#pragma unroll
        for (int off = 1; off < 8; off <<= 1) {
            int y = __shfl_up_sync(0xffu, s, off);
            if (t >= off) s += y;
        }
        wsum[t] = s;
    }
    __syncthreads();
    int woff = (t >= 32) ? wsum[(t >> 5) - 1] : 0;
    int incl = x + woff;
    if (i < NN) g_rowstart[i] = incl - v;
    if (t == 255) g_bsum[b] = incl;
}

__global__ void k_scan2(int nblk) {
    __shared__ int wsum[8];
    int t = threadIdx.x;
    int v = (t < nblk) ? g_bsum[t] : 0;
    int x = v;
#pragma unroll
    for (int off = 1; off < 32; off <<= 1) {
        int y = __shfl_up_sync(0xffffffffu, x, off);
        if ((t & 31) >= off) x += y;
    }
    if ((t & 31) == 31) wsum[t >> 5] = x;
    __syncthreads();
    if (t < 8) {
        int s = wsum[t];
#pragma unroll
        for (int off = 1; off < 8; off <<= 1) {
            int y = __shfl_up_sync(0xffu, s, off);
            if (t >= off) s += y;
        }
        wsum[t] = s;
    }
    __syncthreads();
    int woff = (t >= 32) ? wsum[(t >> 5) - 1] : 0;
    int incl = x + woff;
    g_boff[t] = incl - v;
    if (t == 255) g_boff[256] = incl;
}

__global__ void k_scan3() {
    int b = blockIdx.x, t = threadIdx.x;
    int i = b * 256 + t;
    if (i < NN) {
        int r = g_rowstart[i] + g_boff[b];
        g_rowstart[i] = r;
        g_cursor[i] = r;
    }
    if (b == 0 && t == 0) g_rowstart[NN] = g_boff[256];
}

__global__ void k_scatter() {
    int e = blockIdx.x * 256 + threadIdx.x;
    if (e >= EE) return;
    int d = g_dst[e];
    int pos = atomicAdd(&g_cursor[d], 1);
    g_eids[pos] = e;
    g_pos[e] = pos;
    g_src_csr[pos] = g_src[e];
}

// ---------------- TF32 GEMM (dual mode + optional relu), cp.async double-buffered ----------------
// block tile 128x128, K-step 32, 4 warps (2x2), warp tile 64x64
static constexpr int LDA = 36;
static constexpr int LDB = 132;
static constexpr int LDS = 132;
static constexpr int GEMM_SMEM = (2 * 128 * LDA + 2 * 32 * LDB) * 4;  // 70656 B

template <bool RELU>
__global__ void __launch_bounds__(128, 2)
k_gemm_tf32(const float* __restrict__ A, const float* B,
            const float* bias, float* Cout,
            int M, int Nc, int K,
            const float* B2, const float* bias2, float* Cout2)
{
    extern __shared__ float sm[];
    float* As = sm;
    float* Bs = sm + 2 * 128 * LDA;

    int tid = threadIdx.x;
    int wid = tid >> 5;
    int row0 = blockIdx.y * 128;
    int col0;
    if (B2) {
        col0 = 0;
        if (blockIdx.x) { B = B2; bias = bias2; Cout = Cout2; }
    } else {
        col0 = blockIdx.x * 128;
    }
    int warp_m = wid >> 1;
    int warp_n = wid & 1;

    wmma::fragment<wmma::accumulator, 16, 16, 8, float> acc[4][4];
#pragma unroll
    for (int i = 0; i < 4; i++)
#pragma unroll
        for (int j = 0; j < 4; j++) wmma::fill_fragment(acc[i][j], 0.f);

    const int NKt = K >> 5;

    auto load_tile = [&](int kt, int buf) {
        float* Ad = As + buf * 128 * LDA;
        float* Bd = Bs + buf * 32 * LDB;
#pragma unroll
        for (int j = 0; j < 8; j++) {
            int idx = tid + j * 128;
            int r = idx >> 3;
            int c4 = (idx & 7) << 2;
            int rr = row0 + r;
            rr = (rr < M) ? rr : 0;
            cp16(Ad + r * LDA + c4, A + (size_t)rr * K + (kt << 5) + c4);
        }
#pragma unroll
        for (int j = 0; j < 8; j++) {
            int idx = tid + j * 128;
            int r = idx >> 5;
            int c4 = (idx & 31) << 2;
            cp16(Bd + r * LDB + c4, B + (size_t)((kt << 5) + r) * Nc + col0 + c4);
        }
    };

    load_tile(0, 0);
    cp_commit();

    for (int kt = 0; kt < NKt; kt++) {
        int buf = kt & 1;
        if (kt + 1 < NKt) load_tile(kt + 1, buf ^ 1);
        cp_commit();
        cp_wait1();
        __syncthreads();

        float* Ab = As + buf * 128 * LDA;
        float* Bb = Bs + buf * 32 * LDB;
#pragma unroll
        for (int kk = 0; kk < 4; kk++) {
            wmma::fragment<wmma::matrix_a, 16, 16, 8, wmma::precision::tf32, wmma::row_major> af[4];
            wmma::fragment<wmma::matrix_b, 16, 16, 8, wmma::precision::tf32, wmma::row_major> bf[4];
#pragma unroll
            for (int i = 0; i < 4; i++) {
                wmma::load_matrix_sync(af[i], Ab + (warp_m * 64 + i * 16) * LDA + kk * 8, LDA);
#pragma unroll
                for (int t = 0; t < af[i].num_elements; t++)
                    af[i].x[t] = wmma::__float_to_tf32(af[i].x[t]);
            }
#pragma unroll
            for (int j = 0; j < 4; j++) {
                wmma::load_matrix_sync(bf[j], Bb + (kk * 8) * LDB + warp_n * 64 + j * 16, LDB);
#pragma unroll
                for (int t = 0; t < bf[j].num_elements; t++)
                    bf[j].x[t] = wmma::__float_to_tf32(bf[j].x[t]);
            }
#pragma unroll
            for (int i = 0; i < 4; i++)
#pragma unroll
                for (int j = 0; j < 4; j++)
                    wmma::mma_sync(acc[i][j], af[i], bf[j], acc[i][j]);
        }
        __syncthreads();
    }

    float* St = As;
#pragma unroll
    for (int ph = 0; ph < 2; ph++) {
        if (warp_m == ph) {
#pragma unroll
            for (int i = 0; i < 4; i++)
#pragma unroll
                for (int j = 0; j < 4; j++)
                    wmma::store_matrix_sync(St + (i * 16) * LDS + warp_n * 64 + j * 16,
                                            acc[i][j], LDS, wmma::mem_row_major);
        }
        __syncthreads();
#pragma unroll
        for (int j = 0; j < 16; j++) {
            int idx = tid + j * 128;
            int lr = idx >> 5;
            int cc = (idx & 31) << 2;
            int g = row0 + ph * 64 + lr;
            if (g < M) {
                float4 o = *(float4*)(St + lr * LDS + cc);
                int c = col0 + cc;
                o.x += bias[c + 0]; o.y += bias[c + 1];
                o.z += bias[c + 2]; o.w += bias[c + 3];
                if (RELU) {
                    o.x = fmaxf(o.x, 0.f); o.y = fmaxf(o.y, 0.f);
                    o.z = fmaxf(o.z, 0.f); o.w = fmaxf(o.w, 0.f);
                }
                *(float4*)(Cout + (size_t)g * Nc + c) = o;
            }
        }
        __syncthreads();
    }
}

// ---------------- v = LayerNorm(h + u) ----------------
__global__ void k_ln_v(const float* __restrict__ h,
                       const float* __restrict__ g, const float* __restrict__ b)
{
    int row = blockIdx.x * 8 + (threadIdx.x >> 5);
    if (row >= NN) return;
    int lane = threadIdx.x & 31;
    const float4* hp = (const float4*)(h + (size_t)row * DD);
    const float4* up = (const float4*)(g_u + (size_t)row * DD);
    float4 hv = hp[lane], uv = up[lane];
    float x0 = hv.x + uv.x, x1 = hv.y + uv.y, x2 = hv.z + uv.z, x3 = hv.w + uv.w;
    float s  = x0 + x1 + x2 + x3;
    float s2 = x0 * x0 + x1 * x1 + x2 * x2 + x3 * x3;
#pragma unroll
    for (int off = 16; off >= 1; off >>= 1) {
        s  += __shfl_xor_sync(0xffffffffu, s,  off);
        s2 += __shfl_xor_sync(0xffffffffu, s2, off);
    }
    float mu  = s * (1.f / 128.f);
    float var = s2 * (1.f / 128.f) - mu * mu;
    float r   = rsqrtf(var + 1e-5f);
    float4 gv = ((const float4*)g)[lane];
    float4 bv = ((const float4*)b)[lane];
    float4 o;
    o.x = (x0 - mu) * r * gv.x + bv.x;
    o.y = (x1 - mu) * r * gv.y + bv.y;
    o.z = (x2 - mu) * r * gv.z + bv.z;
    o.w = (x3 - mu) * r * gv.w + bv.w;
    ((float4*)(g_v + (size_t)row * DD))[lane] = o;
}

// ---------------- edge logits: wmma xe (64 edges/block) + warp-per-edge float4 finish ----------------
static constexpr int EPB = 64;
static constexpr int LDEA = 36;
static constexpr int LDWE = 132;
static constexpr int LDXE = 132;
static constexpr int EDGE_SMEM = (EPB * LDEA + EDD * LDWE + EPB * LDXE + 128) * 4; // 60416 B

__global__ void __launch_bounds__(256)
k_edge_logits(const float* __restrict__ edge_attr,
              const float* __restrict__ We, const float* __restrict__ att)
{
    extern __shared__ float sm[];
    float* ea_sh  = sm;
    float* We_sh  = ea_sh + EPB * LDEA;
    float* xe_sh  = We_sh + EDD * LDWE;
    float* att_sh = xe_sh + EPB * LDXE;

    int tid = threadIdx.x;
    int e0 = blockIdx.x * EPB;

#pragma unroll
    for (int j = 0; j < 2; j++) {
        int idx = tid + j * 256;
        int r = idx >> 3;
        int cc = (idx & 7) << 2;
        float4 v = *(const float4*)(edge_attr + (size_t)(e0 + r) * EDD + cc);
        *(float4*)(ea_sh + r * LDEA + cc) = v;
    }
#pragma unroll
    for (int j = 0; j < 4; j++) {
        int idx = tid + j * 256;
        int r = idx >> 5;
        int cc = (idx & 31) << 2;
        float4 v = *(const float4*)(We + (size_t)r * 128 + cc);
        *(float4*)(We_sh + r * LDWE + cc) = v;
    }
    if (tid < 128) att_sh[tid] = att[tid];
    __syncthreads();

    // xe = ea @ We : m=64, n=128, k=32 (8 warps: 4x2, warp tile 16x64)
    {
        int wid = tid >> 5;
        int warp_m = wid >> 1;
        int warp_n = wid & 1;
        wmma::fragment<wmma::accumulator, 16, 16, 8, float> acc[4];
#pragma unroll
        for (int j = 0; j < 4; j++) wmma::fill_fragment(acc[j], 0.f);
#pragma unroll
        for (int kk = 0; kk < 4; kk++) {
            wmma::fragment<wmma::matrix_a, 16, 16, 8, wmma::precision::tf32, wmma::row_major> af;
            wmma::load_matrix_sync(af, ea_sh + (warp_m * 16) * LDEA + kk * 8, LDEA);
#pragma unroll
            for (int t = 0; t < af.num_elements; t++) af.x[t] = wmma::__float_to_tf32(af.x[t]);
#pragma unroll
            for (int j = 0; j < 4; j++) {
                wmma::fragment<wmma::matrix_b, 16, 16, 8, wmma::precision::tf32, wmma::row_major> bf;
                wmma::load_matrix_sync(bf, We_sh + (kk * 8) * LDWE + warp_n * 64 + j * 16, LDWE);
#pragma unroll
                for (int t = 0; t < bf.num_elements; t++) bf.x[t] = wmma::__float_to_tf32(bf.x[t]);
                wmma::mma_sync(acc[j], af, bf, acc[j]);
            }
        }
#pragma unroll
        for (int j = 0; j < 4; j++)
            wmma::store_matrix_sync(xe_sh + (warp_m * 16) * LDXE + warp_n * 64 + j * 16,
                                    acc[j], LDXE, wmma::mem_row_major);
    }
    __syncthreads();

    // finish: warp-per-edge, float4 per lane
    {
        int wid  = tid >> 5;
        int lane = tid & 31;
        int c4 = lane << 2;
        float4 attv = *(float4*)(att_sh + c4);

#pragma unroll
        for (int it = 0; it < EPB / 8; it++) {
            int le = it * 8 + wid;
            int e  = e0 + le;
            int s  = g_src[e];
            int d  = g_dst[e];
            float4 xe4 = *(float4*)(xe_sh + le * LDXE + c4);
            float4 xl4 = *(const float4*)(g_xl + (size_t)s * DD + c4);
            float4 xr4 = *(const float4*)(g_xr + (size_t)d * DD + c4);
            float x0 = xe4.x + xl4.x + xr4.x;
            float x1 = xe4.y + xl4.y + xr4.y;
            float x2 = xe4.z + xl4.z + xr4.z;
            float x3 = xe4.w + xl4.w + xr4.w;
            x0 = (x0 > 0.f) ? x0 : 0.2f * x0;
            x1 = (x1 > 0.f) ? x1 : 0.2f * x1;
            x2 = (x2 > 0.f) ? x2 : 0.2f * x2;
            x3 = (x3 > 0.f) ? x3 : 0.2f * x3;
            float p = x0 * attv.x + x1 * attv.y + x2 * attv.z + x3 * attv.w;
            p += __shfl_down_sync(0xffffffffu, p, 2);
            p += __shfl_down_sync(0xffffffffu, p, 1);
            if ((lane & 3) == 0) {
                int pos = g_pos[e];
                g_logits[(size_t)pos * HH + (lane >> 2)] = p;
            }
        }
    }
}

// ---------------- per-node softmax + aggregation + LN (shuffle reductions, __expf) ----------------
__global__ void __launch_bounds__(128)
k_node(const float* __restrict__ bias_out,
       const float* __restrict__ ln_g, const float* __restrict__ ln_b,
       float* __restrict__ out, float* __restrict__ alpha_out)
{
    __shared__ float swarp[32];
    __shared__ float sacc[4 * 128];
    __shared__ float invden[8];

    int n   = blockIdx.x;
    int tid = threadIdx.x;
    int wid  = tid >> 5;
    int lane = tid & 31;
    int start = g_rowstart[n];
    int deg   = g_rowstart[n + 1] - start;

    float s = 0.f;
    size_t base = (size_t)start * HH;
    for (int idx = tid; idx < deg * HH; idx += 128)
        s += __expf(g_logits[base + idx]);
    s += __shfl_xor_sync(0xffffffffu, s, 16);
    s += __shfl_xor_sync(0xffffffffu, s, 8);
    if (lane < 8) swarp[wid * 8 + lane] = s;
    __syncthreads();
    if (tid < 8) {
        float t = swarp[tid] + swarp[8 + tid] + swarp[16 + tid] + swarp[24 + tid];
        invden[tid] = (t > 0.f) ? 1.f / t : 0.f;
    }
    __syncthreads();

    int c4 = lane << 2;
    int hd = lane >> 2;
    float id2 = invden[hd];
    float4 acc4 = make_float4(0.f, 0.f, 0.f, 0.f);
    for (int i = wid; i < deg; i += 4) {
        int p = start + i;
        float a = __expf(g_logits[(size_t)p * HH + hd]) * id2;
        int srcn = g_src_csr[p];
        if ((lane & 3) == 0) alpha_out[(size_t)g_eids[p] * HH + hd] = a;
        float4 x = *(const float4*)(g_xl + (size_t)srcn * DD + c4);
        acc4.x = fmaf(a, x.x, acc4.x);
        acc4.y = fmaf(a, x.y, acc4.y);
        acc4.z = fmaf(a, x.z, acc4.z);
        acc4.w = fmaf(a, x.w, acc4.w);
    }
    *(float4*)(sacc + wid * 128 + c4) = acc4;
    __syncthreads();

    int c = tid;
    float wv = sacc[c] + sacc[128 + c] + sacc[256 + c] + sacc[384 + c]
             + bias_out[c] + g_v[(size_t)n * DD + c];

    float r1 = wv;
#pragma unroll
    for (int off = 16; off >= 1; off >>= 1)
        r1 += __shfl_xor_sync(0xffffffffu, r1, off);
    if (lane == 0) swarp[wid] = r1;
    __syncthreads();
    float mu = (swarp[0] + swarp[1] + swarp[2] + swarp[3]) * (1.f / 128.f);
    float dv = wv - mu;
    float r2 = dv * dv;
#pragma unroll
    for (int off = 16; off >= 1; off >>= 1)
        r2 += __shfl_xor_sync(0xffffffffu, r2, off);
    __syncthreads();
    if (lane == 0) swarp[wid] = r2;
    __syncthreads();
    float var = (swarp[0] + swarp[1] + swarp[2] + swarp[3]) * (1.f / 128.f);
    float r = rsqrtf(var + 1e-5f);
    out[(size_t)n * DD + c] = dv * r * ln_g[c] + ln_b[c];
}

// ---------------- launch ----------------
extern "C" void kernel_launch(void* const* d_in, const int* in_sizes, int n_in,
                              void* d_out, int out_size)
{
    const float* h_ptr     = (const float*)d_in[0];
    const void*  ei        = d_in[1];
    const float* edge_attr = (const float*)d_in[2];
    const float* w1        = (const float*)d_in[3];
    const float* b1        = (const float*)d_in[4];
    const float* w2        = (const float*)d_in[5];
    const float* b2        = (const float*)d_in[6];
    const float* ln_g      = (const float*)d_in[7];
    const float* ln_b      = (const float*)d_in[8];
    const float* Wl        = (const float*)d_in[9];
    const float* bl        = (const float*)d_in[10];
    const float* Wr        = (const float*)d_in[11];
    const float* br        = (const float*)d_in[12];
    const float* We        = (const float*)d_in[13];
    const float* att       = (const float*)d_in[14];
    const float* bias_out  = (const float*)d_in[15];

    float* out = (float*)d_out;
    float* alpha_out = out + ((size_t)out_size - (size_t)EE * HH);

    void *p_act, *p_u, *p_v, *p_xl, *p_xr;
    cudaGetSymbolAddress(&p_act, g_act);
    cudaGetSymbolAddress(&p_u,   g_u);
    cudaGetSymbolAddress(&p_v,   g_v);
    cudaGetSymbolAddress(&p_xl,  g_xl);
    cudaGetSymbolAddress(&p_xr,  g_xr);
    float* act = (float*)p_act;
    float* u   = (float*)p_u;
    float* v   = (float*)p_v;
    float* xl  = (float*)p_xl;
    float* xr  = (float*)p_xr;

    cudaFuncSetAttribute(k_gemm_tf32<true>,  cudaFuncAttributeMaxDynamicSharedMemorySize, GEMM_SMEM);
    cudaFuncSetAttribute(k_gemm_tf32<false>, cudaFuncAttributeMaxDynamicSharedMemorySize, GEMM_SMEM);
    cudaFuncSetAttribute(k_edge_logits,      cudaFuncAttributeMaxDynamicSharedMemorySize, EDGE_SMEM);

    int nblk = (NN + 255) / 256;  // 196

    k_zero_deg<<<nblk, 256>>>();
    k_detect<<<1, 1>>>(ei);
    k_convert<<<(EE + 255) / 256, 256>>>(ei);

    // profiled slot #4 -> FFN1
    dim3 g1(HIDN / 128, (NN + 127) / 128);
    k_gemm_tf32<true><<<g1, 128, GEMM_SMEM>>>(h_ptr, w1, b1, act, NN, HIDN, DD,
                                              nullptr, nullptr, nullptr);

    k_scan1<<<nblk, 256>>>();
    k_scan2<<<1, 256>>>(nblk);
    k_scan3<<<nblk, 256>>>();
    k_scatter<<<(EE + 255) / 256, 256>>>();

    dim3 g2(DD / 128, (NN + 127) / 128);
    k_gemm_tf32<false><<<g2, 128, GEMM_SMEM>>>(act, w2, b2, u, NN, DD, HIDN,
                                               nullptr, nullptr, nullptr);
    k_ln_v<<<(NN + 7) / 8, 256>>>(h_ptr, ln_g, ln_b);

    // fused Wl/Wr projection
    dim3 gd(2, (NN + 127) / 128);
    k_gemm_tf32<false><<<gd, 128, GEMM_SMEM>>>(v, Wl, bl, xl, NN, DD, DD, Wr, br, xr);

    k_edge_logits<<<EE / EPB, 256, EDGE_SMEM>>>(edge_attr, We, att);

    k_node<<<NN, 128>>>(bias_out, ln_g, ln_b, out, alpha_out);
}